// round 5
// baseline (speedup 1.0000x reference)
#include <cuda_runtime.h>
#include <stdint.h>

// GraphSAGE 4-layer, dense adj. Round 5: aggregation on int8 tensor cores.
// adj -> 16-bit fixed (static scale, 2 s8 bytes); z -> 16-bit per-column scale.
// adj@z = (A1Z1*65536 + (A1Z0+A0Z1)*256)*lsb_a*lsb_z, exact s32 accumulation.

static constexpr int MROWS = 8192;
static constexpr float A_MAX = 3.0e-4f;            // bound on adj entries
static constexpr float S_A   = 32512.0f / A_MAX;
static constexpr float LSB_A = A_MAX / 32512.0f;

__device__ float g_y [8192 * 128];
__device__ float g_zf[8192 * 128];
__device__ float g_h1[8192 * 128];
__device__ float g_h2[8192 * 128];
__device__ __align__(16) int8_t g_zb1[128 * 8192];   // z hi byte, transposed [n][k]
__device__ __align__(16) int8_t g_zb0[128 * 8192];   // z lo byte
__device__ unsigned g_cmax[512];                     // 4 layers x 128 col |z| max

__device__ __forceinline__ uint32_t smem_u32(const void* p) {
    uint32_t a;
    asm("{ .reg .u64 t; cvta.to.shared.u64 t, %1; cvt.u32.u64 %0, t; }"
        : "=r"(a) : "l"(p));
    return a;
}
__device__ __forceinline__ void ldsm_x4(uint32_t* r, uint32_t addr) {
    asm volatile("ldmatrix.sync.aligned.m8n8.x4.shared.b16 {%0,%1,%2,%3}, [%4];"
                 : "=r"(r[0]), "=r"(r[1]), "=r"(r[2]), "=r"(r[3]) : "r"(addr));
}
__device__ __forceinline__ void mma_s8(int* d, const uint32_t* a,
                                       uint32_t b0, uint32_t b1) {
    asm volatile(
        "mma.sync.aligned.m16n8k32.row.col.s32.s8.s8.s32 "
        "{%0,%1,%2,%3}, {%4,%5,%6,%7}, {%8,%9}, {%0,%1,%2,%3};"
        : "+r"(d[0]), "+r"(d[1]), "+r"(d[2]), "+r"(d[3])
        : "r"(a[0]), "r"(a[1]), "r"(a[2]), "r"(a[3]), "r"(b0), "r"(b1));
}
__device__ __forceinline__ void cp16(uint32_t dst, const void* src) {
    asm volatile("cp.async.ca.shared.global [%0], [%1], 16;" :: "r"(dst), "l"(src));
}
#define CP_COMMIT() asm volatile("cp.async.commit_group;" ::: "memory")
#define CP_WAIT1()  asm volatile("cp.async.wait_group 1;" ::: "memory")

__global__ void clear_k(unsigned* c) { c[threadIdx.x] = 0u; }

// ── projection: D = A@B (+bias); ZOUT also records per-column |D| max ──
template <int BN, int NT, bool BIAS, bool ZOUT>
__global__ __launch_bounds__(NT) void gemm_k(
    const float* __restrict__ A, int lda, const float* __restrict__ B,
    const float* __restrict__ bias, float* __restrict__ D,
    unsigned* __restrict__ cmax, int K)
{
    constexpr int BM = 64, BK = 16, TM = 4, TN = 8;
    constexpr int AF4 = (BM * BK / 4) / NT;
    constexpr int BF4 = (BK * BN / 4) / NT;
    __shared__ float As[BK][BM];
    __shared__ float Bs[BK][BN];
    __shared__ unsigned scm[BN];

    const int tid = threadIdx.x;
    const int tx = tid % (BN / TN), ty = tid / (BN / TN);
    const int m0 = blockIdx.x * BM;
    if (ZOUT) for (int j = tid; j < BN; j += NT) scm[j] = 0u;

    float acc[TM][TN];
#pragma unroll
    for (int i = 0; i < TM; i++)
#pragma unroll
        for (int j = 0; j < TN; j++) acc[i][j] = 0.f;

    float4 ra[AF4], rb[BF4];
    const int nkt = K / BK;
#pragma unroll
    for (int u = 0; u < AF4; u++) {
        int id = tid + u * NT, row = id >> 2, k4 = id & 3;
        ra[u] = *reinterpret_cast<const float4*>(A + (size_t)(m0 + row) * lda + k4 * 4);
    }
#pragma unroll
    for (int u = 0; u < BF4; u++) {
        int id = tid + u * NT, row = id / (BN / 4), c4 = id % (BN / 4);
        rb[u] = *reinterpret_cast<const float4*>(B + (size_t)row * BN + c4 * 4);
    }
    for (int kt = 0; kt < nkt; ++kt) {
#pragma unroll
        for (int u = 0; u < AF4; u++) {
            int id = tid + u * NT, row = id >> 2, k4 = id & 3;
            As[k4 * 4 + 0][row] = ra[u].x; As[k4 * 4 + 1][row] = ra[u].y;
            As[k4 * 4 + 2][row] = ra[u].z; As[k4 * 4 + 3][row] = ra[u].w;
        }
#pragma unroll
        for (int u = 0; u < BF4; u++) {
            int id = tid + u * NT, row = id / (BN / 4), c4 = id % (BN / 4);
            *reinterpret_cast<float4*>(&Bs[row][c4 * 4]) = rb[u];
        }
        __syncthreads();
        if (kt + 1 < nkt) {
            const int kb = (kt + 1) * BK;
#pragma unroll
            for (int u = 0; u < AF4; u++) {
                int id = tid + u * NT, row = id >> 2, k4 = id & 3;
                ra[u] = *reinterpret_cast<const float4*>(
                    A + (size_t)(m0 + row) * lda + kb + k4 * 4);
            }
#pragma unroll
            for (int u = 0; u < BF4; u++) {
                int id = tid + u * NT, row = id / (BN / 4), c4 = id % (BN / 4);
                rb[u] = *reinterpret_cast<const float4*>(
                    B + (size_t)(kb + row) * BN + c4 * 4);
            }
        }
#pragma unroll
        for (int k = 0; k < BK; k++) {
            float a[TM], b[TN];
            *reinterpret_cast<float4*>(a) = *reinterpret_cast<const float4*>(&As[k][ty * TM]);
            *reinterpret_cast<float4*>(b) = *reinterpret_cast<const float4*>(&Bs[k][tx * TN]);
            *reinterpret_cast<float4*>(b + 4) = *reinterpret_cast<const float4*>(&Bs[k][tx * TN + 4]);
#pragma unroll
            for (int i = 0; i < TM; i++)
#pragma unroll
                for (int j = 0; j < TN; j++) acc[i][j] = fmaf(a[i], b[j], acc[i][j]);
        }
        __syncthreads();
    }
#pragma unroll
    for (int i = 0; i < TM; i++) {
        const int row = m0 + ty * TM + i;
#pragma unroll
        for (int j = 0; j < TN; j += 4) {
            const int col = tx * TN + j;
            float4 v = make_float4(acc[i][j], acc[i][j+1], acc[i][j+2], acc[i][j+3]);
            if (BIAS) {
                float4 c = *reinterpret_cast<const float4*>(bias + col);
                v.x += c.x; v.y += c.y; v.z += c.z; v.w += c.w;
            }
            *reinterpret_cast<float4*>(D + (size_t)row * BN + col) = v;
        }
    }
    if (ZOUT) {
#pragma unroll
        for (int j = 0; j < TN; j++) {
            float m = fmaxf(fmaxf(fabsf(acc[0][j]), fabsf(acc[1][j])),
                            fmaxf(fabsf(acc[2][j]), fabsf(acc[3][j])));
            atomicMax(&scm[tx * TN + j], __float_as_uint(m));
        }
        __syncthreads();
        for (int j = tid; j < BN; j += NT) atomicMax(&cmax[j], scm[j]);
    }
}

// ── quantize + transpose z: fp32 [8192,BN] -> s8 hi/lo [BN][8192] ──
template <int BN>
__global__ __launch_bounds__(256) void quant_k(
    const float* __restrict__ zf, const unsigned* __restrict__ cm,
    int8_t* __restrict__ zb1, int8_t* __restrict__ zb0)
{
    __shared__ int8_t s1[32][144], s0[32][144];
    const int tid = threadIdx.x;
    const int k0 = blockIdx.x * 128, n0 = blockIdx.y * 32;
    const int r = tid >> 3, cq = tid & 7;
    float inv[4];
#pragma unroll
    for (int j = 0; j < 4; j++) {
        float c = __uint_as_float(cm[n0 + cq * 4 + j]);
        inv[j] = c > 0.f ? 32512.0f / c : 0.f;
    }
#pragma unroll
    for (int u = 0; u < 4; u++) {
        int row = u * 32 + r;
        float4 v = *reinterpret_cast<const float4*>(zf + (size_t)(k0 + row) * BN + n0 + cq * 4);
        float vv[4] = {v.x, v.y, v.z, v.w};
#pragma unroll
        for (int j = 0; j < 4; j++) {
            int q = __float2int_rn(vv[j] * inv[j]);
            int b1 = (q + 128) >> 8, b0 = q - (b1 << 8);
            s1[cq * 4 + j][row] = (int8_t)b1;
            s0[cq * 4 + j][row] = (int8_t)b0;
        }
    }
    __syncthreads();
    const int n = tid >> 3, q8 = tid & 7;
    *reinterpret_cast<uint4*>(zb1 + (size_t)(n0 + n) * MROWS + k0 + q8 * 16) =
        *reinterpret_cast<const uint4*>(&s1[n][q8 * 16]);
    *reinterpret_cast<uint4*>(zb0 + (size_t)(n0 + n) * MROWS + k0 + q8 * 16) =
        *reinterpret_cast<const uint4*>(&s0[n][q8 * 16]);
}

// ── aggregation: out = act(adj @ z + y), int8 MMA ──
template <int BN>
__global__ __launch_bounds__(256) void agg_i8(
    const float* __restrict__ adj,
    const int8_t* __restrict__ zb1, const int8_t* __restrict__ zb0,
    const unsigned* __restrict__ cm, const float* __restrict__ y,
    float* __restrict__ out, int relu)
{
    constexpr int BM = 64, BK = 64, NCH = MROWS / BK;
    constexpr int LDS_ = 80;
    constexpr int ATILE = BM * LDS_, ASTG = 2 * ATILE;
    constexpr int BTILE = BN * LDS_, BSTG = 2 * BTILE;
    constexpr int BOFF = 2 * ASTG;
    constexpr int WCW = BN / 4, NTN = WCW / 8, NBL = NTN / 2, BU = BN / 64;

    extern __shared__ __align__(128) char sm[];
    const uint32_t smb = smem_u32(sm);
    const int tid = threadIdx.x, m0 = blockIdx.x * BM;
    const int w = tid >> 5, lane = tid & 31;
    const int wr = w >> 2, wc = w & 3;

    int acc1[2][NTN][4], acc2[2][NTN][4];
#pragma unroll
    for (int mt = 0; mt < 2; mt++)
#pragma unroll
        for (int nt = 0; nt < NTN; nt++)
#pragma unroll
            for (int q = 0; q < 4; q++) { acc1[mt][nt][q] = 0; acc2[mt][nt][q] = 0; }

    float4 ra[4];
    auto prefA = [&](int chunk) {
        const size_t kb = (size_t)chunk * BK;
#pragma unroll
        for (int u = 0; u < 4; u++) {
            int id = tid + u * 256, row = id >> 4, c = id & 15;
            ra[u] = *reinterpret_cast<const float4*>(
                adj + (size_t)(m0 + row) * MROWS + kb + c * 4);
        }
    };
    auto stsA = [&](int sa) {
        const uint32_t base = smb + sa * ASTG;
#pragma unroll
        for (int u = 0; u < 4; u++) {
            int id = tid + u * 256, row = id >> 4, c = id & 15;
            float vv[4] = {ra[u].x, ra[u].y, ra[u].z, ra[u].w};
            uint32_t p1 = 0, p0 = 0;
#pragma unroll
            for (int j = 0; j < 4; j++) {
                int q = __float2int_rn(vv[j] * S_A);
                q = min(max(q, 0), 32639);
                int b1 = (q + 128) >> 8, b0 = q - (b1 << 8);
                p1 |= (uint32_t)(b1 & 255) << (8 * j);
                p0 |= (uint32_t)(b0 & 255) << (8 * j);
            }
            uint32_t off = row * LDS_ + c * 4;
            asm volatile("st.shared.b32 [%0], %1;" :: "r"(base + off), "r"(p1));
            asm volatile("st.shared.b32 [%0], %1;" :: "r"(base + ATILE + off), "r"(p0));
        }
    };
    auto issueB = [&](int chunk) {
        const uint32_t base = smb + BOFF + (chunk % 3) * BSTG;
        const size_t kb = (size_t)chunk * BK;
#pragma unroll
        for (int u = 0; u < BU; u++) {
            int id = tid + u * 256, n = id >> 2, c = id & 3;
            uint32_t off = n * LDS_ + c * 16;
            size_t ge = (size_t)n * MROWS + kb + c * 16;
            cp16(base + off, zb1 + ge);
            cp16(base + BTILE + off, zb0 + ge);
        }
    };

    const uint32_t a_lrow = (uint32_t)(wr * 32 + (lane & 15)) * LDS_ + (lane >> 4) * 16;
    uint32_t b_lrow[NBL];
#pragma unroll
    for (int g = 0; g < NBL; g++) {
        int nl = wc * WCW + g * 16 + (lane & 7) + ((lane >> 4) & 1) * 8;
        b_lrow[g] = (uint32_t)nl * LDS_ + ((lane >> 3) & 1) * 16;
    }

    auto compute = [&](int sa, int sb) {
        const uint32_t ab = smb + sa * ASTG;
        const uint32_t bb = smb + BOFF + sb * BSTG;
#pragma unroll
        for (int ks = 0; ks < 2; ks++) {
            uint32_t a1f[2][4], a0f[2][4];
#pragma unroll
            for (int mt = 0; mt < 2; mt++) {
                uint32_t ao = ab + a_lrow + mt * (16 * LDS_) + ks * 32;
                ldsm_x4(a1f[mt], ao);
                ldsm_x4(a0f[mt], ao + ATILE);
            }
            uint32_t b1f[NBL][4], b0f[NBL][4];
#pragma unroll
            for (int g = 0; g < NBL; g++) {
                uint32_t bo = bb + b_lrow[g] + ks * 32;
                ldsm_x4(b1f[g], bo);
                ldsm_x4(b0f[g], bo + BTILE);
            }
#pragma unroll
            for (int mt = 0; mt < 2; mt++)
#pragma unroll
                for (int nt = 0; nt < NTN; nt++) {
                    const int g = nt >> 1, p = (nt & 1) * 2;
                    mma_s8(acc1[mt][nt], a1f[mt], b1f[g][p], b1f[g][p + 1]);
                    mma_s8(acc2[mt][nt], a1f[mt], b0f[g][p], b0f[g][p + 1]);
                    mma_s8(acc2[mt][nt], a0f[mt], b1f[g][p], b1f[g][p + 1]);
                }
        }
    };

    issueB(0); CP_COMMIT();
    issueB(1); CP_COMMIT();
    prefA(0);
    for (int i = 0; i < NCH; i++) {
        const int sa = i & 1, sb = i % 3;
        CP_WAIT1();
        stsA(sa);
        __syncthreads();
        if (i + 1 < NCH) prefA(i + 1);
        if (i + 2 < NCH) issueB(i + 2);
        CP_COMMIT();
        compute(sa, sb);
    }

    const int gg = lane >> 2, cp2 = (lane & 3) * 2;
#pragma unroll
    for (int mt = 0; mt < 2; mt++) {
        const int r0 = m0 + wr * 32 + mt * 16 + gg;
#pragma unroll
        for (int nt = 0; nt < NTN; nt++) {
            const int col = wc * WCW + nt * 8 + cp2;
            const float s0 = __uint_as_float(cm[col])     * (LSB_A / 32512.0f);
            const float s1 = __uint_as_float(cm[col + 1]) * (LSB_A / 32512.0f);
#pragma unroll
            for (int half = 0; half < 2; half++) {
                const size_t row = (size_t)(r0 + half * 8);
                float2 yv = *reinterpret_cast<const float2*>(y + row * BN + col);
                float v0 = ((float)acc1[mt][nt][2*half]   * 65536.f +
                            (float)acc2[mt][nt][2*half]   * 256.f) * s0 + yv.x;
                float v1 = ((float)acc1[mt][nt][2*half+1] * 65536.f +
                            (float)acc2[mt][nt][2*half+1] * 256.f) * s1 + yv.y;
                if (relu) { v0 = fmaxf(v0, 0.f); v1 = fmaxf(v1, 0.f); }
                *reinterpret_cast<float2*>(out + row * BN + col) = make_float2(v0, v1);
            }
        }
    }
}

extern "C" void kernel_launch(void* const* d_in, const int* in_sizes, int n_in,
                              void* d_out, int out_size)
{
    const float* x   = (const float*)d_in[0];
    const float* adj = (const float*)d_in[1];
    const float* W1  = (const float*)d_in[2];
    const float* b1  = (const float*)d_in[3];
    const float* W2  = (const float*)d_in[4];
    const float* b2  = (const float*)d_in[5];
    const float* W3  = (const float*)d_in[6];
    const float* b3  = (const float*)d_in[7];
    const float* W4  = (const float*)d_in[8];
    const float* b4  = (const float*)d_in[9];
    float* out = (float*)d_out;

    float *y, *zf, *h1, *h2;
    int8_t *zb1, *zb0;
    unsigned* cmax;
    cudaGetSymbolAddress((void**)&y,   g_y);
    cudaGetSymbolAddress((void**)&zf,  g_zf);
    cudaGetSymbolAddress((void**)&h1,  g_h1);
    cudaGetSymbolAddress((void**)&h2,  g_h2);
    cudaGetSymbolAddress((void**)&zb1, g_zb1);
    cudaGetSymbolAddress((void**)&zb0, g_zb0);
    cudaGetSymbolAddress((void**)&cmax, g_cmax);

    constexpr int SM128 = 2 * (2 * 64 * 80) + 3 * (2 * 128 * 80);  // 81920
    constexpr int SM64  = 2 * (2 * 64 * 80) + 3 * (2 * 64 * 80);   // 51200
    cudaFuncSetAttribute(agg_i8<128>, cudaFuncAttributeMaxDynamicSharedMemorySize, SM128);
    cudaFuncSetAttribute(agg_i8<64>,  cudaFuncAttributeMaxDynamicSharedMemorySize, SM64);

    const dim3 pg(MROWS / 64);
    const dim3 ag(MROWS / 64);
    const dim3 qg128(MROWS / 128, 4), qg64(MROWS / 128, 2);

    clear_k<<<1, 512>>>(cmax);

    gemm_k<128,256,false,true ><<<pg,256>>>(x, 256, W1 + 256*128, nullptr, zf, cmax, 256);
    gemm_k<128,256,true, false><<<pg,256>>>(x, 256, W1, b1, y, nullptr, 256);
    quant_k<128><<<qg128,256>>>(zf, cmax, zb1, zb0);
    agg_i8<128><<<ag,256,SM128>>>(adj, zb1, zb0, cmax, y, h1, 1);

    gemm_k<128,256,false,true ><<<pg,256>>>(h1, 128, W2 + 128*128, nullptr, zf, cmax+128, 128);
    gemm_k<128,256,true, false><<<pg,256>>>(h1, 128, W2, b2, y, nullptr, 128);
    quant_k<128><<<qg128,256>>>(zf, cmax+128, zb1, zb0);
    agg_i8<128><<<ag,256,SM128>>>(adj, zb1, zb0, cmax+128, y, h2, 1);

    gemm_k<128,256,false,true ><<<pg,256>>>(h2, 128, W3 + 128*128, nullptr, zf, cmax+256, 128);
    gemm_k<128,256,true, false><<<pg,256>>>(h2, 128, W3, b3, y, nullptr, 128);
    quant_k<128><<<qg128,256>>>(zf, cmax+256, zb1, zb0);
    agg_i8<128><<<ag,256,SM128>>>(adj, zb1, zb0, cmax+256, y, h1, 1);

    gemm_k<64,128,false,true ><<<pg,128>>>(h1, 128, W4 + 128*64, nullptr, zf, cmax+384, 128);
    gemm_k<64,128,true, false><<<pg,128>>>(h1, 128, W4, b4, y, nullptr, 128);
    quant_k<64><<<qg64,256>>>(zf, cmax+384, zb1, zb0);
    agg_i8<64><<<ag,256,SM64>>>(adj, zb1, zb0, cmax+384, y, out, 0);
}

// round 6
// speedup vs baseline: 2.4109x; 2.4109x over previous
#include <cuda_runtime.h>
#include <cuda_bf16.h>
#include <stdint.h>

// GraphSAGE 4-layer, dense adj. N=8192, F: 256->128->128->64.
// Per layer: h = act( h@W_self + adj @ (h@W_neigh) + b ).
// Aggregation: mma.sync bf16 3-term split (AhBh + AhBl + AlBh, fp32 acc).
// R6: agg mainloop restructured — compute first, convert/STS after (overlap),
// cp.async 3-stage ring for B, BK=64.

static constexpr int MROWS = 8192;

__device__ float g_y [8192 * 128];
__device__ float g_h1[8192 * 128];
__device__ float g_h2[8192 * 128];
__device__ __nv_bfloat16 g_zh[8192 * 128];
__device__ __nv_bfloat16 g_zl[8192 * 128];

__device__ __forceinline__ uint32_t smem_u32(const void* p) {
    uint32_t a;
    asm("{ .reg .u64 t; cvta.to.shared.u64 t, %1; cvt.u32.u64 %0, t; }"
        : "=r"(a) : "l"(p));
    return a;
}
__device__ __forceinline__ uint32_t pack_hi2(float a, float b, float& ra, float& rb) {
    __nv_bfloat16 ha = __float2bfloat16(a), hb = __float2bfloat16(b);
    ra = a - __bfloat162float(ha);
    rb = b - __bfloat162float(hb);
    __nv_bfloat162 t(ha, hb);
    return *reinterpret_cast<uint32_t*>(&t);
}
__device__ __forceinline__ uint32_t pack2(float a, float b) {
    __nv_bfloat162 t(__float2bfloat16(a), __float2bfloat16(b));
    return *reinterpret_cast<uint32_t*>(&t);
}
__device__ __forceinline__ void ldsm_x4(uint32_t* r, uint32_t addr) {
    asm volatile("ldmatrix.sync.aligned.m8n8.x4.shared.b16 {%0,%1,%2,%3}, [%4];"
                 : "=r"(r[0]), "=r"(r[1]), "=r"(r[2]), "=r"(r[3]) : "r"(addr));
}
__device__ __forceinline__ void ldsm_x4_t(uint32_t* r, uint32_t addr) {
    asm volatile("ldmatrix.sync.aligned.m8n8.x4.trans.shared.b16 {%0,%1,%2,%3}, [%4];"
                 : "=r"(r[0]), "=r"(r[1]), "=r"(r[2]), "=r"(r[3]) : "r"(addr));
}
__device__ __forceinline__ void mma_bf16(float* d, const uint32_t* a,
                                         uint32_t b0, uint32_t b1) {
    asm volatile(
        "mma.sync.aligned.m16n8k16.row.col.f32.bf16.bf16.f32 "
        "{%0,%1,%2,%3}, {%4,%5,%6,%7}, {%8,%9}, {%0,%1,%2,%3};"
        : "+f"(d[0]), "+f"(d[1]), "+f"(d[2]), "+f"(d[3])
        : "r"(a[0]), "r"(a[1]), "r"(a[2]), "r"(a[3]), "r"(b0), "r"(b1));
}
__device__ __forceinline__ void cp16(uint32_t dst, const void* src) {
    asm volatile("cp.async.ca.shared.global [%0], [%1], 16;" :: "r"(dst), "l"(src));
}
#define CP_COMMIT() asm volatile("cp.async.commit_group;" ::: "memory")
#define CP_WAIT1()  asm volatile("cp.async.wait_group 1;" ::: "memory")

// ── aggregation: out = act(adj @ z + y) ──
// adj fp32 [8192,8192]; zh/zl bf16 [8192,BN] row-major; y fp32 [8192,BN].
template <int BN>
__global__ __launch_bounds__(256) void agg_k(
    const float* __restrict__ adj,
    const __nv_bfloat16* __restrict__ zh,
    const __nv_bfloat16* __restrict__ zl,
    const float* __restrict__ y,
    float* __restrict__ out,
    int relu)
{
    constexpr int BM = 64, BK = 64, NCH = MROWS / BK;   // 128 chunks
    constexpr int LDA = 144;                            // 64 bf16 row + 16B pad
    constexpr int ATILE = BM * LDA;                     // 9216 per hi/lo tile
    constexpr int ASTG = 2 * ATILE;                     // 18432 per stage
    constexpr int LDB = BN * 2 + 16;
    constexpr int BTILE = BK * LDB;
    constexpr int BSTG = 2 * BTILE;
    constexpr int BOFF = 2 * ASTG;                      // A: 2 stages
    constexpr int CW = BN / 4;                          // warp column span
    constexpr int NTN = CW / 8;                         // n8 tiles (4 / 2)
    constexpr int NBL = NTN / 2;                        // B ldsm per kstep (2 / 1)
    constexpr int BCP = (BK * BN * 2 / 16) / 256;       // cp16 per thread per array

    extern __shared__ __align__(128) char sm[];
    const uint32_t smb = smem_u32(sm);
    const int tid = threadIdx.x, m0 = blockIdx.x * BM;
    const int w = tid >> 5, lane = tid & 31;
    const int wr = w >> 2, wc = w & 3;

    float acc[2][NTN][4];
#pragma unroll
    for (int mt = 0; mt < 2; mt++)
#pragma unroll
        for (int nt = 0; nt < NTN; nt++)
#pragma unroll
            for (int q = 0; q < 4; q++) acc[mt][nt][q] = 0.f;

    float4 ra[4];                                       // one chunk of A (fp32)

    auto prefA = [&](int chunk) {
        const size_t kb = (size_t)chunk * BK;
#pragma unroll
        for (int u = 0; u < 4; u++) {
            int id = tid + u * 256, row = id >> 4, c = id & 15;
            ra[u] = *reinterpret_cast<const float4*>(
                adj + (size_t)(m0 + row) * MROWS + kb + c * 4);
        }
    };
    auto cvtSTS = [&](int sa) {
        const uint32_t base = smb + sa * ASTG;
#pragma unroll
        for (int u = 0; u < 4; u++) {
            int id = tid + u * 256, row = id >> 4, c = id & 15;
            float r0, r1, r2, r3;
            uint32_t h01 = pack_hi2(ra[u].x, ra[u].y, r0, r1);
            uint32_t h23 = pack_hi2(ra[u].z, ra[u].w, r2, r3);
            uint32_t off = (uint32_t)(row * LDA + c * 8);
            *reinterpret_cast<uint2*>(sm + sa * ASTG + off) = make_uint2(h01, h23);
            *reinterpret_cast<uint2*>(sm + sa * ASTG + ATILE + off) =
                make_uint2(pack2(r0, r1), pack2(r2, r3));
        }
        (void)base;
    };
    auto issueB = [&](int chunk) {
        const uint32_t base = smb + BOFF + (chunk % 3) * BSTG;
        const size_t kb = (size_t)chunk * BK;
        constexpr int CPR = BN / 8;                     // cp16 per row
#pragma unroll
        for (int u = 0; u < BCP; u++) {
            int id = tid + u * 256, krow = id / CPR, c = id % CPR;
            uint32_t off = (uint32_t)(krow * LDB + c * 16);
            size_t ge = (kb + krow) * BN + c * 8;
            cp16(base + off, zh + ge);
            cp16(base + BTILE + off, zl + ge);
        }
    };

    const uint32_t a_lrow =
        (uint32_t)(wr * 32 + (lane & 15)) * LDA + (lane >> 4) * 16;

    auto compute = [&](int sa, int sb) {
        const uint32_t ab = smb + sa * ASTG;
        const uint32_t bb = smb + BOFF + sb * BSTG;
#pragma unroll
        for (int ks = 0; ks < 4; ks++) {
            uint32_t ah[2][4], al[2][4];
#pragma unroll
            for (int mt = 0; mt < 2; mt++) {
                uint32_t ao = ab + a_lrow + mt * (16 * LDA) + ks * 32;
                ldsm_x4(ah[mt], ao);
                ldsm_x4(al[mt], ao + ATILE);
            }
            uint32_t bh[NBL][4], bl[NBL][4];
#pragma unroll
            for (int bt = 0; bt < NBL; bt++) {
                int krow = ks * 16 + (lane & 15);
                int ncol = wc * CW + bt * 16 + (lane >> 4) * 8;
                uint32_t bo = bb + (uint32_t)(krow * LDB + ncol * 2);
                ldsm_x4_t(bh[bt], bo);
                ldsm_x4_t(bl[bt], bo + BTILE);
            }
#pragma unroll
            for (int mt = 0; mt < 2; mt++)
#pragma unroll
                for (int nt = 0; nt < NTN; nt++) {
                    const int g = nt >> 1, p = (nt & 1) * 2;
                    mma_bf16(acc[mt][nt], ah[mt], bh[g][p], bh[g][p + 1]);
                    mma_bf16(acc[mt][nt], ah[mt], bl[g][p], bl[g][p + 1]);
                    mma_bf16(acc[mt][nt], al[mt], bh[g][p], bh[g][p + 1]);
                }
        }
    };

    // prologue
    issueB(0); CP_COMMIT();
    issueB(1); CP_COMMIT();
    prefA(0);
    cvtSTS(0);          // stage 0 ready
    prefA(1);           // chunk 1 in registers

    for (int i = 0; i < NCH; i++) {
        const int sa = i & 1, sb = i % 3;
        CP_WAIT1();                       // B(i) landed
        __syncthreads();                  // A stage sa + B stage sb visible
        compute(sa, sb);
        if (i + 2 < NCH) { issueB(i + 2); CP_COMMIT(); }
        if (i + 1 < NCH) {
            cvtSTS((i + 1) & 1);          // from ra (chunk i+1), other A stage
            if (i + 2 < NCH) prefA(i + 2);
        }
    }

    // epilogue: + y, relu, store fp32
    const int g = lane >> 2, cp2 = (lane & 3) * 2;
#pragma unroll
    for (int mt = 0; mt < 2; mt++) {
        const int r0 = m0 + wr * 32 + mt * 16 + g;
#pragma unroll
        for (int nt = 0; nt < NTN; nt++) {
            const int col = wc * CW + nt * 8 + cp2;
#pragma unroll
            for (int half = 0; half < 2; half++) {
                const size_t row = (size_t)(r0 + half * 8);
                float2 yv = *reinterpret_cast<const float2*>(y + row * BN + col);
                float v0 = acc[mt][nt][2 * half + 0] + yv.x;
                float v1 = acc[mt][nt][2 * half + 1] + yv.y;
                if (relu) { v0 = fmaxf(v0, 0.f); v1 = fmaxf(v1, 0.f); }
                *reinterpret_cast<float2*>(out + row * BN + col) =
                    make_float2(v0, v1);
            }
        }
    }
}

// ── SIMT fp32 projection GEMM (small K); ZOUT writes bf16 hi/lo row-major ──
template <int BN, int NT, bool BIAS, bool ZOUT>
__global__ __launch_bounds__(NT) void gemm_k(
    const float* __restrict__ A, int lda,
    const float* __restrict__ B,
    const float* __restrict__ bias,
    float* __restrict__ D,
    __nv_bfloat16* __restrict__ zh,
    __nv_bfloat16* __restrict__ zl,
    int K)
{
    constexpr int BM = 64, BK = 16, TM = 4, TN = 8;
    constexpr int AF4 = (BM * BK / 4) / NT;
    constexpr int BF4 = (BK * BN / 4) / NT;
    __shared__ float As[BK][BM];
    __shared__ float Bs[BK][BN];

    const int tid = threadIdx.x;
    const int tx = tid % (BN / TN), ty = tid / (BN / TN);
    const int m0 = blockIdx.x * BM;

    float acc[TM][TN];
#pragma unroll
    for (int i = 0; i < TM; i++)
#pragma unroll
        for (int j = 0; j < TN; j++) acc[i][j] = 0.f;

    float4 ra[AF4], rb[BF4];
    const int nkt = K / BK;
#pragma unroll
    for (int u = 0; u < AF4; u++) {
        int id = tid + u * NT, row = id >> 2, k4 = id & 3;
        ra[u] = *reinterpret_cast<const float4*>(A + (size_t)(m0 + row) * lda + k4 * 4);
    }
#pragma unroll
    for (int u = 0; u < BF4; u++) {
        int id = tid + u * NT, row = id / (BN / 4), c4 = id % (BN / 4);
        rb[u] = *reinterpret_cast<const float4*>(B + (size_t)row * BN + c4 * 4);
    }
    for (int kt = 0; kt < nkt; ++kt) {
#pragma unroll
        for (int u = 0; u < AF4; u++) {
            int id = tid + u * NT, row = id >> 2, k4 = id & 3;
            As[k4 * 4 + 0][row] = ra[u].x; As[k4 * 4 + 1][row] = ra[u].y;
            As[k4 * 4 + 2][row] = ra[u].z; As[k4 * 4 + 3][row] = ra[u].w;
        }
#pragma unroll
        for (int u = 0; u < BF4; u++) {
            int id = tid + u * NT, row = id / (BN / 4), c4 = id % (BN / 4);
            *reinterpret_cast<float4*>(&Bs[row][c4 * 4]) = rb[u];
        }
        __syncthreads();
        if (kt + 1 < nkt) {
            const int kb = (kt + 1) * BK;
#pragma unroll
            for (int u = 0; u < AF4; u++) {
                int id = tid + u * NT, row = id >> 2, k4 = id & 3;
                ra[u] = *reinterpret_cast<const float4*>(
                    A + (size_t)(m0 + row) * lda + kb + k4 * 4);
            }
#pragma unroll
            for (int u = 0; u < BF4; u++) {
                int id = tid + u * NT, row = id / (BN / 4), c4 = id % (BN / 4);
                rb[u] = *reinterpret_cast<const float4*>(
                    B + (size_t)(kb + row) * BN + c4 * 4);
            }
        }
#pragma unroll
        for (int k = 0; k < BK; k++) {
            float a[TM], b[TN];
            *reinterpret_cast<float4*>(a) = *reinterpret_cast<const float4*>(&As[k][ty * TM]);
            *reinterpret_cast<float4*>(b) = *reinterpret_cast<const float4*>(&Bs[k][tx * TN]);
            *reinterpret_cast<float4*>(b + 4) = *reinterpret_cast<const float4*>(&Bs[k][tx * TN + 4]);
#pragma unroll
            for (int i = 0; i < TM; i++)
#pragma unroll
                for (int j = 0; j < TN; j++) acc[i][j] = fmaf(a[i], b[j], acc[i][j]);
        }
        __syncthreads();
    }
#pragma unroll
    for (int i = 0; i < TM; i++) {
        const int row = m0 + ty * TM + i;
        if (ZOUT) {
#pragma unroll
            for (int j = 0; j < TN; j += 2) {
                const int col = tx * TN + j;
                float r0, r1;
                uint32_t h = pack_hi2(acc[i][j], acc[i][j + 1], r0, r1);
                *reinterpret_cast<uint32_t*>(zh + (size_t)row * BN + col) = h;
                *reinterpret_cast<uint32_t*>(zl + (size_t)row * BN + col) = pack2(r0, r1);
            }
        } else {
#pragma unroll
            for (int j = 0; j < TN; j += 4) {
                const int col = tx * TN + j;
                float4 v = make_float4(acc[i][j], acc[i][j+1], acc[i][j+2], acc[i][j+3]);
                if (BIAS) {
                    float4 c = *reinterpret_cast<const float4*>(bias + col);
                    v.x += c.x; v.y += c.y; v.z += c.z; v.w += c.w;
                }
                *reinterpret_cast<float4*>(D + (size_t)row * BN + col) = v;
            }
        }
    }
}

extern "C" void kernel_launch(void* const* d_in, const int* in_sizes, int n_in,
                              void* d_out, int out_size)
{
    const float* x   = (const float*)d_in[0];
    const float* adj = (const float*)d_in[1];
    const float* W1  = (const float*)d_in[2];
    const float* b1  = (const float*)d_in[3];
    const float* W2  = (const float*)d_in[4];
    const float* b2  = (const float*)d_in[5];
    const float* W3  = (const float*)d_in[6];
    const float* b3  = (const float*)d_in[7];
    const float* W4  = (const float*)d_in[8];
    const float* b4  = (const float*)d_in[9];
    float* out = (float*)d_out;

    float *y, *h1, *h2;
    __nv_bfloat16 *zh, *zl;
    cudaGetSymbolAddress((void**)&y,  g_y);
    cudaGetSymbolAddress((void**)&h1, g_h1);
    cudaGetSymbolAddress((void**)&h2, g_h2);
    cudaGetSymbolAddress((void**)&zh, g_zh);
    cudaGetSymbolAddress((void**)&zl, g_zl);

    // smem: A 2 stages (hi+lo) + B 3 stages (hi+lo)
    constexpr int SM128 = 2 * (2 * 64 * 144) + 3 * (2 * 64 * (128 * 2 + 16)); // 141312
    constexpr int SM64  = 2 * (2 * 64 * 144) + 3 * (2 * 64 * (64 * 2 + 16));  //  92160
    cudaFuncSetAttribute(agg_k<128>, cudaFuncAttributeMaxDynamicSharedMemorySize, SM128);
    cudaFuncSetAttribute(agg_k<64>,  cudaFuncAttributeMaxDynamicSharedMemorySize, SM64);

    const dim3 pg(MROWS / 64);
    const dim3 ag(MROWS / 64);

    // Layer 1 (256 -> 128, relu)
    gemm_k<128,256,false,true ><<<pg,256>>>(x, 256, W1 + 256*128, nullptr, nullptr, zh, zl, 256);
    gemm_k<128,256,true, false><<<pg,256>>>(x, 256, W1, b1, y, nullptr, nullptr, 256);
    agg_k<128><<<ag,256,SM128>>>(adj, zh, zl, y, h1, 1);

    // Layer 2 (128 -> 128, relu)
    gemm_k<128,256,false,true ><<<pg,256>>>(h1, 128, W2 + 128*128, nullptr, nullptr, zh, zl, 128);
    gemm_k<128,256,true, false><<<pg,256>>>(h1, 128, W2, b2, y, nullptr, nullptr, 128);
    agg_k<128><<<ag,256,SM128>>>(adj, zh, zl, y, h2, 1);

    // Layer 3 (128 -> 128, relu)
    gemm_k<128,256,false,true ><<<pg,256>>>(h2, 128, W3 + 128*128, nullptr, nullptr, zh, zl, 128);
    gemm_k<128,256,true, false><<<pg,256>>>(h2, 128, W3, b3, y, nullptr, nullptr, 128);
    agg_k<128><<<ag,256,SM128>>>(adj, zh, zl, y, h1, 1);

    // Layer 4 (128 -> 64, no relu) -> d_out
    gemm_k<64,128,false,true ><<<pg,128>>>(h1, 128, W4 + 128*64, nullptr, nullptr, zh, zl, 128);
    gemm_k<64,128,true, false><<<pg,128>>>(h1, 128, W4, b4, y, nullptr, nullptr, 128);
    agg_k<64><<<ag,256,SM64>>>(adj, zh, zl, y, out, 0);
}